// round 1
// baseline (speedup 1.0000x reference)
#include <cuda_runtime.h>
#include <math.h>

#define B_TOT   16384
#define D_IN    512
#define H_MID   256
#define R_OUT   95
#define BM      32
#define NTHR    256
#define SMEM_FLOATS 36864   // 147456 bytes dynamic

__device__ __forceinline__ float wred(float v) {
#pragma unroll
    for (int o = 16; o > 0; o >>= 1) v += __shfl_xor_sync(0xffffffffu, v, o);
    return v;
}

// One MLP projection for a 32-row tile:
//   X = h@W1 + b1 ; LN ; GELU(exact erf) ; m = X@W2 + b2  -> s_m (32 x 64)
__device__ __forceinline__ void projection(
    const float* __restrict__ hsrc,
    const float* __restrict__ W1, const float* __restrict__ b1,
    const float* __restrict__ lg, const float* __restrict__ lb,
    const float* __restrict__ W2, const float* __restrict__ b2,
    float* s_h, float* s_w, float* s_m, int row0, int tid)
{
    const int tx = tid & 31, ty = tid >> 5;

    // load h tile (rows are contiguous: 32*512 floats)
    {
        const float4* hg = reinterpret_cast<const float4*>(hsrc + (size_t)row0 * D_IN);
        float4* sh4 = reinterpret_cast<float4*>(s_h);
#pragma unroll
        for (int t = 0; t < (BM * D_IN / 4) / NTHR; ++t)
            sh4[tid + t * NTHR] = hg[tid + t * NTHR];
    }

    float acc[4][8];
#pragma unroll
    for (int i = 0; i < 4; i++)
#pragma unroll
        for (int j = 0; j < 8; j++) acc[i][j] = 0.f;

    // GEMM1: (32 x 512) @ (512 x 256), smem-tiled over k in chunks of 64
    for (int kt = 0; kt < D_IN; kt += 64) {
        __syncthreads();   // protect s_w reuse (prev tile / prev projection's act)
        {
            const float4* wg = reinterpret_cast<const float4*>(W1 + (size_t)kt * H_MID);
            float4* sw4 = reinterpret_cast<float4*>(s_w);
#pragma unroll
            for (int t = 0; t < (64 * H_MID / 4) / NTHR; ++t)
                sw4[tid + t * NTHR] = wg[tid + t * NTHR];
        }
        __syncthreads();
#pragma unroll 4
        for (int k4 = 0; k4 < 64; k4 += 4) {
            float4 a4[4];
#pragma unroll
            for (int i = 0; i < 4; i++)
                a4[i] = *reinterpret_cast<const float4*>(&s_h[(ty * 4 + i) * D_IN + kt + k4]);
#pragma unroll
            for (int kk = 0; kk < 4; kk++) {
                const float a0 = ((const float*)&a4[0])[kk];
                const float a1 = ((const float*)&a4[1])[kk];
                const float a2 = ((const float*)&a4[2])[kk];
                const float a3 = ((const float*)&a4[3])[kk];
#pragma unroll
                for (int j = 0; j < 8; j++) {
                    const float b = s_w[(k4 + kk) * H_MID + tx + 32 * j];
                    acc[0][j] += a0 * b;
                    acc[1][j] += a1 * b;
                    acc[2][j] += a2 * b;
                    acc[3][j] += a3 * b;
                }
            }
        }
    }
    __syncthreads();

    // bias + LayerNorm (per row, each row owned by one warp) + exact GELU
    float cb[8], cg[8], cbe[8];
#pragma unroll
    for (int j = 0; j < 8; j++) {
        const int c = tx + 32 * j;
        cb[j] = b1[c]; cg[j] = lg[c]; cbe[j] = lb[c];
    }
#pragma unroll
    for (int i = 0; i < 4; i++) {
        float s = 0.f, ss = 0.f;
#pragma unroll
        for (int j = 0; j < 8; j++) {
            const float x = acc[i][j] + cb[j];
            acc[i][j] = x; s += x; ss += x * x;
        }
        s = wred(s); ss = wred(ss);
        const float mean = s * (1.f / H_MID);
        const float var  = ss * (1.f / H_MID) - mean * mean;
        const float rstd = rsqrtf(var + 1e-5f);
#pragma unroll
        for (int j = 0; j < 8; j++) {
            const float x = (acc[i][j] - mean) * rstd * cg[j] + cbe[j];
            acc[i][j] = 0.5f * x * (1.f + erff(x * 0.70710678118654752440f));
        }
    }

    // activation tile -> s_w, stride 257 (bank-conflict-free on both sides)
#pragma unroll
    for (int i = 0; i < 4; i++)
#pragma unroll
        for (int j = 0; j < 8; j++)
            s_w[(ty * 4 + i) * 257 + tx + 32 * j] = acc[i][j];
    __syncthreads();

    // GEMM2: (32 x 256) @ (256 x 64)   W2 streams from L2 (64 KB, hot)
    const int rr  = tid >> 3;        // output row 0..31
    const int cb2 = (tid & 7) * 8;   // output col base
    float m[8];
#pragma unroll
    for (int j = 0; j < 8; j++) m[j] = b2[cb2 + j];
#pragma unroll 8
    for (int n = 0; n < H_MID; n++) {
        const float a = s_w[rr * 257 + n];
        const float4 w0 = *reinterpret_cast<const float4*>(W2 + n * 64 + cb2);
        const float4 w1 = *reinterpret_cast<const float4*>(W2 + n * 64 + cb2 + 4);
        m[0] += a * w0.x; m[1] += a * w0.y; m[2] += a * w0.z; m[3] += a * w0.w;
        m[4] += a * w1.x; m[5] += a * w1.y; m[6] += a * w1.z; m[7] += a * w1.w;
    }
#pragma unroll
    for (int j = 0; j < 8; j++) s_m[rr * 64 + cb2 + j] = m[j];
}

__global__ __launch_bounds__(NTHR, 1)
void clifford_fused_kernel(
    const float* __restrict__ hp, const float* __restrict__ hv,
    const float* __restrict__ Wp1, const float* __restrict__ bp1,
    const float* __restrict__ lgp, const float* __restrict__ lbp,
    const float* __restrict__ Wp2, const float* __restrict__ bp2,
    const float* __restrict__ Wv1, const float* __restrict__ bv1,
    const float* __restrict__ lgv, const float* __restrict__ lbv,
    const float* __restrict__ Wv2, const float* __restrict__ bv2,
    const float* __restrict__ T, const float* __restrict__ gw,
    float* __restrict__ out)
{
    extern __shared__ float smem[];
    float* s_h  = smem;            // 16384 floats (h tile)   [later aliased]
    float* s_w  = smem + 16384;    // 16384 floats (W1 tile / act tile)
    float* s_mp = smem + 32768;    // 2048
    float* s_mv = smem + 34816;    // 2048
    float* s_T  = smem;            // alias of s_h: 95 * 65 = 6175 floats (padded)
    float* s_u  = smem + 8192;     // alias of s_h upper half: 2048 floats

    const int tid  = threadIdx.x;
    const int row0 = blockIdx.x * BM;

    projection(hp, Wp1, bp1, lgp, lbp, Wp2, bp2, s_h, s_w, s_mp, row0, tid);
    __syncthreads();
    projection(hv, Wv1, bv1, lgv, lbv, Wv2, bv2, s_h, s_w, s_mv, row0, tid);
    __syncthreads();

    // load T (95 x 64) into padded smem (stride 65 -> conflict-free in final GEMM)
    for (int t = tid; t < R_OUT * 64; t += NTHR) {
        const int r = t >> 6, q = t & 63;
        s_T[r * 65 + q] = T[t];
    }

    // Triple-product collapse: u[b,k,j] = sum_i p_i * SG[i][j] * w[XI[i][j]],
    // w[m] = sum_j' SG[m][j'] * gw[XI[m][j']] * v[j']
    {
        const int row = tid >> 3, k = tid & 7;
        float p[8], v[8];
#pragma unroll
        for (int i = 0; i < 8; i++) {
            p[i] = s_mp[row * 64 + k * 8 + i];
            v[i] = s_mv[row * 64 + k * 8 + i];
        }
        // Cl(3,0) signed-permutation tables, basis [1,e1,e2,e3,e12,e13,e23,e123]
        const float SG[8][8] = {
            { 1, 1, 1, 1, 1, 1, 1, 1},
            { 1, 1, 1, 1, 1, 1, 1, 1},
            { 1,-1, 1, 1,-1,-1, 1,-1},
            { 1,-1,-1, 1, 1,-1,-1, 1},
            { 1,-1, 1, 1,-1,-1, 1,-1},
            { 1,-1,-1, 1, 1,-1,-1, 1},
            { 1, 1,-1, 1,-1, 1,-1,-1},
            { 1, 1,-1, 1,-1, 1,-1,-1},
        };
        const int XI[8][8] = {
            {0,1,2,3,4,5,6,7},
            {1,0,4,5,2,3,7,6},
            {2,4,0,6,1,7,3,5},
            {3,5,6,0,7,1,2,4},
            {4,2,1,7,0,6,5,3},
            {5,3,7,1,6,0,4,2},
            {6,7,3,2,5,4,0,1},
            {7,6,5,4,3,2,1,0},
        };
        float g[8];
#pragma unroll
        for (int n = 0; n < 8; n++) g[n] = gw[n];
        float w[8];
#pragma unroll
        for (int mm = 0; mm < 8; mm++) {
            float a = 0.f;
#pragma unroll
            for (int jp = 0; jp < 8; jp++)
                a += SG[mm][jp] * g[XI[mm][jp]] * v[jp];
            w[mm] = a;
        }
#pragma unroll
        for (int j = 0; j < 8; j++) {
            float a = 0.f;
#pragma unroll
            for (int i = 0; i < 8; i++)
                a += p[i] * SG[i][j] * w[XI[i][j]];
            s_u[row * 64 + k * 8 + j] = a;
        }
    }
    __syncthreads();

    // Final tiny GEMM: out[b,r] = (1/8) * u[b,:] . T[r,:]
    for (int idx = tid; idx < BM * R_OUT; idx += NTHR) {
        const int b = idx / R_OUT;
        const int r = idx - b * R_OUT;
        const float* up = &s_u[b * 64];
        const float* tp = &s_T[r * 65];
        float a = 0.f;
#pragma unroll
        for (int q = 0; q < 64; q++) a += up[q] * tp[q];
        out[(size_t)(row0 + b) * R_OUT + r] = a * 0.125f;
    }
}

extern "C" void kernel_launch(void* const* d_in, const int* in_sizes, int n_in,
                              void* d_out, int out_size)
{
    (void)in_sizes; (void)n_in; (void)out_size;
    const float* hp  = (const float*)d_in[0];
    const float* hv  = (const float*)d_in[1];
    const float* Wp1 = (const float*)d_in[2];
    const float* bp1 = (const float*)d_in[3];
    const float* lgp = (const float*)d_in[4];
    const float* lbp = (const float*)d_in[5];
    const float* Wp2 = (const float*)d_in[6];
    const float* bp2 = (const float*)d_in[7];
    const float* Wv1 = (const float*)d_in[8];
    const float* bv1 = (const float*)d_in[9];
    const float* lgv = (const float*)d_in[10];
    const float* lbv = (const float*)d_in[11];
    const float* Wv2 = (const float*)d_in[12];
    const float* bv2 = (const float*)d_in[13];
    const float* T   = (const float*)d_in[14];
    const float* gw  = (const float*)d_in[15];
    float* out = (float*)d_out;

    cudaFuncSetAttribute(clifford_fused_kernel,
                         cudaFuncAttributeMaxDynamicSharedMemorySize,
                         SMEM_FLOATS * 4);
    clifford_fused_kernel<<<B_TOT / BM, NTHR, SMEM_FLOATS * 4>>>(
        hp, hv, Wp1, bp1, lgp, lbp, Wp2, bp2,
        Wv1, bv1, lgv, lbv, Wv2, bv2, T, gw, out);
}

// round 3
// speedup vs baseline: 1.0281x; 1.0281x over previous
#include <cuda_runtime.h>
#include <math.h>

#define B_TOT   16384
#define D_IN    512
#define H_MID   256
#define R_OUT   95
#define BM      32
#define NTHR    256
#define KC      64                       // k-chunk for both h and W1 staging
#define SMEM_FLOATS 22528                // 90112 bytes dynamic

__device__ __forceinline__ float wred(float v) {
#pragma unroll
    for (int o = 16; o > 0; o >>= 1) v += __shfl_xor_sync(0xffffffffu, v, o);
    return v;
}

// One MLP projection for a 32-row tile:
//   X = h@W1 + b1 ; LN ; GELU(exact erf) ; m = X@W2 + b2  -> s_m (32 x 64)
__device__ __forceinline__ void projection(
    const float* __restrict__ hsrc,
    const float* __restrict__ W1, const float* __restrict__ b1,
    const float* __restrict__ lg, const float* __restrict__ lb,
    const float* __restrict__ W2, const float* __restrict__ b2,
    float* s_h, float* s_w, float* s_m, int row0, int tid)
{
    const int tx = tid & 31, ty = tid >> 5;

    float acc[4][8];
#pragma unroll
    for (int i = 0; i < 4; i++)
#pragma unroll
        for (int j = 0; j < 8; j++) acc[i][j] = 0.f;

    // GEMM1: (32 x 512) @ (512 x 256), both operands staged per 64-deep k-chunk
    for (int kt = 0; kt < D_IN; kt += KC) {
        __syncthreads();   // protect s_h/s_w reuse from previous chunk readers
        // h chunk: 32 rows x 64 k = 512 float4
        {
            float4* sh4 = reinterpret_cast<float4*>(s_h);
#pragma unroll
            for (int t = 0; t < 2; ++t) {
                const int idx  = tid + t * NTHR;      // 0..511
                const int row  = idx >> 4;            // 16 f4 per row
                const int col4 = idx & 15;
                sh4[row * 16 + col4] = *reinterpret_cast<const float4*>(
                    hsrc + (size_t)(row0 + row) * D_IN + kt + col4 * 4);
            }
        }
        // W1 chunk: 64 x 256 contiguous = 4096 float4
        {
            const float4* wg = reinterpret_cast<const float4*>(W1 + (size_t)kt * H_MID);
            float4* sw4 = reinterpret_cast<float4*>(s_w);
#pragma unroll
            for (int t = 0; t < (KC * H_MID / 4) / NTHR; ++t)
                sw4[tid + t * NTHR] = wg[tid + t * NTHR];
        }
        __syncthreads();
#pragma unroll 4
        for (int k4 = 0; k4 < KC; k4 += 4) {
            float4 a4[4];
#pragma unroll
            for (int i = 0; i < 4; i++)
                a4[i] = *reinterpret_cast<const float4*>(&s_h[(ty * 4 + i) * KC + k4]);
#pragma unroll
            for (int kk = 0; kk < 4; kk++) {
                const float a0 = ((const float*)&a4[0])[kk];
                const float a1 = ((const float*)&a4[1])[kk];
                const float a2 = ((const float*)&a4[2])[kk];
                const float a3 = ((const float*)&a4[3])[kk];
#pragma unroll
                for (int j = 0; j < 8; j++) {
                    const float b = s_w[(k4 + kk) * H_MID + tx + 32 * j];
                    acc[0][j] += a0 * b;
                    acc[1][j] += a1 * b;
                    acc[2][j] += a2 * b;
                    acc[3][j] += a3 * b;
                }
            }
        }
    }
    __syncthreads();

    // bias + LayerNorm (per row, each row owned by one warp) + exact GELU
    float cb[8], cg[8], cbe[8];
#pragma unroll
    for (int j = 0; j < 8; j++) {
        const int c = tx + 32 * j;
        cb[j] = b1[c]; cg[j] = lg[c]; cbe[j] = lb[c];
    }
#pragma unroll
    for (int i = 0; i < 4; i++) {
        float s = 0.f, ss = 0.f;
#pragma unroll
        for (int j = 0; j < 8; j++) {
            const float x = acc[i][j] + cb[j];
            acc[i][j] = x; s += x; ss += x * x;
        }
        s = wred(s); ss = wred(ss);
        const float mean = s * (1.f / H_MID);
        const float var  = ss * (1.f / H_MID) - mean * mean;
        const float rstd = rsqrtf(var + 1e-5f);
#pragma unroll
        for (int j = 0; j < 8; j++) {
            const float x = (acc[i][j] - mean) * rstd * cg[j] + cbe[j];
            acc[i][j] = 0.5f * x * (1.f + erff(x * 0.70710678118654752440f));
        }
    }

    // activation tile -> s_w, stride 260 (keeps conflict-free column mapping)
#pragma unroll
    for (int i = 0; i < 4; i++)
#pragma unroll
        for (int j = 0; j < 8; j++)
            s_w[(ty * 4 + i) * 260 + tx + 32 * j] = acc[i][j];
    __syncthreads();

    // GEMM2: (32 x 256) @ (256 x 64)   W2 streams from L2 (64 KB, hot)
    const int rr  = tid >> 3;        // output row 0..31
    const int cb2 = (tid & 7) * 8;   // output col base
    float m[8];
#pragma unroll
    for (int j = 0; j < 8; j++) m[j] = b2[cb2 + j];
#pragma unroll 8
    for (int n = 0; n < H_MID; n++) {
        const float a = s_w[rr * 260 + n];
        const float4 w0 = *reinterpret_cast<const float4*>(W2 + n * 64 + cb2);
        const float4 w1 = *reinterpret_cast<const float4*>(W2 + n * 64 + cb2 + 4);
        m[0] += a * w0.x; m[1] += a * w0.y; m[2] += a * w0.z; m[3] += a * w0.w;
        m[4] += a * w1.x; m[5] += a * w1.y; m[6] += a * w1.z; m[7] += a * w1.w;
    }
#pragma unroll
    for (int j = 0; j < 8; j++) s_m[rr * 64 + cb2 + j] = m[j];
}

__global__ __launch_bounds__(NTHR, 2)
void clifford_fused_kernel(
    const float* __restrict__ hp, const float* __restrict__ hv,
    const float* __restrict__ Wp1, const float* __restrict__ bp1,
    const float* __restrict__ lgp, const float* __restrict__ lbp,
    const float* __restrict__ Wp2, const float* __restrict__ bp2,
    const float* __restrict__ Wv1, const float* __restrict__ bv1,
    const float* __restrict__ lgv, const float* __restrict__ lbv,
    const float* __restrict__ Wv2, const float* __restrict__ bv2,
    const float* __restrict__ T, const float* __restrict__ gw,
    float* __restrict__ out)
{
    extern __shared__ float smem[];
    float* s_w  = smem;            // 16384 floats: W1 chunks / act tile (32x260)
    float* s_h  = smem + 16384;    // 2048 floats: h chunk (32x64)
    float* s_mp = smem + 18432;    // 2048
    float* s_mv = smem + 20480;    // 2048
    float* s_T  = smem;            // alias s_w: 95*65 = 6175 floats
    float* s_u  = smem + 8192;     // alias s_w upper: 2048 floats

    const int tid  = threadIdx.x;
    const int row0 = blockIdx.x * BM;

    projection(hp, Wp1, bp1, lgp, lbp, Wp2, bp2, s_h, s_w, s_mp, row0, tid);
    __syncthreads();
    projection(hv, Wv1, bv1, lgv, lbv, Wv2, bv2, s_h, s_w, s_mv, row0, tid);
    __syncthreads();

    // load T (95 x 64) into padded smem (stride 65 -> conflict-free final GEMM)
    for (int t = tid; t < R_OUT * 64; t += NTHR) {
        const int r = t >> 6, q = t & 63;
        s_T[r * 65 + q] = T[t];
    }

    // Triple-product collapse: u[b,k,j] = sum_i p_i * SG[i][j] * w[XI[i][j]],
    // w[m] = sum_j' SG[m][j'] * gw[XI[m][j']] * v[j']
    {
        const int row = tid >> 3, k = tid & 7;
        float p[8], v[8];
#pragma unroll
        for (int i = 0; i < 8; i++) {
            p[i] = s_mp[row * 64 + k * 8 + i];
            v[i] = s_mv[row * 64 + k * 8 + i];
        }
        // Cl(3,0) signed-permutation tables, basis [1,e1,e2,e3,e12,e13,e23,e123]
        const float SG[8][8] = {
            { 1, 1, 1, 1, 1, 1, 1, 1},
            { 1, 1, 1, 1, 1, 1, 1, 1},
            { 1,-1, 1, 1,-1,-1, 1,-1},
            { 1,-1,-1, 1, 1,-1,-1, 1},
            { 1,-1, 1, 1,-1,-1, 1,-1},
            { 1,-1,-1, 1, 1,-1,-1, 1},
            { 1, 1,-1, 1,-1, 1,-1,-1},
            { 1, 1,-1, 1,-1, 1,-1,-1},
        };
        const int XI[8][8] = {
            {0,1,2,3,4,5,6,7},
            {1,0,4,5,2,3,7,6},
            {2,4,0,6,1,7,3,5},
            {3,5,6,0,7,1,2,4},
            {4,2,1,7,0,6,5,3},
            {5,3,7,1,6,0,4,2},
            {6,7,3,2,5,4,0,1},
            {7,6,5,4,3,2,1,0},
        };
        float g[8];
#pragma unroll
        for (int n = 0; n < 8; n++) g[n] = gw[n];
        float w[8];
#pragma unroll
        for (int mm = 0; mm < 8; mm++) {
            float a = 0.f;
#pragma unroll
            for (int jp = 0; jp < 8; jp++)
                a += SG[mm][jp] * g[XI[mm][jp]] * v[jp];
            w[mm] = a;
        }
#pragma unroll
        for (int j = 0; j < 8; j++) {
            float a = 0.f;
#pragma unroll
            for (int i = 0; i < 8; i++)
                a += p[i] * SG[i][j] * w[XI[i][j]];
            s_u[row * 64 + k * 8 + j] = a;
        }
    }
    __syncthreads();

    // Final tiny GEMM: out[b,r] = (1/8) * u[b,:] . T[r,:]
    for (int idx = tid; idx < BM * R_OUT; idx += NTHR) {
        const int b = idx / R_OUT;
        const int r = idx - b * R_OUT;
        const float* up = &s_u[b * 64];
        const float* tp = &s_T[r * 65];
        float a = 0.f;
#pragma unroll
        for (int q = 0; q < 64; q++) a += up[q] * tp[q];
        out[(size_t)(row0 + b) * R_OUT + r] = a * 0.125f;
    }
}

extern "C" void kernel_launch(void* const* d_in, const int* in_sizes, int n_in,
                              void* d_out, int out_size)
{
    (void)in_sizes; (void)n_in; (void)out_size;
    const float* hp  = (const float*)d_in[0];
    const float* hv  = (const float*)d_in[1];
    const float* Wp1 = (const float*)d_in[2];
    const float* bp1 = (const float*)d_in[3];
    const float* lgp = (const float*)d_in[4];
    const float* lbp = (const float*)d_in[5];
    const float* Wp2 = (const float*)d_in[6];
    const float* bp2 = (const float*)d_in[7];
    const float* Wv1 = (const float*)d_in[8];
    const float* bv1 = (const float*)d_in[9];
    const float* lgv = (const float*)d_in[10];
    const float* lbv = (const float*)d_in[11];
    const float* Wv2 = (const float*)d_in[12];
    const float* bv2 = (const float*)d_in[13];
    const float* T   = (const float*)d_in[14];
    const float* gw  = (const float*)d_in[15];
    float* out = (float*)d_out;

    cudaFuncSetAttribute(clifford_fused_kernel,
                         cudaFuncAttributeMaxDynamicSharedMemorySize,
                         SMEM_FLOATS * 4);
    clifford_fused_kernel<<<B_TOT / BM, NTHR, SMEM_FLOATS * 4>>>(
        hp, hv, Wp1, bp1, lgp, lbp, Wp2, bp2,
        Wv1, bv1, lgv, lbv, Wv2, bv2, T, gw, out);
}

// round 4
// speedup vs baseline: 1.2957x; 1.2604x over previous
#include <cuda_runtime.h>
#include <math.h>

#define B_TOT   16384
#define D_IN    512
#define H_MID   256
#define R_OUT   95
#define BM      64
#define NTHR    256
#define KC      32
#define SMEM_FLOATS 24960   // 99840 bytes

// ---- f32x2 packed helpers (sm_100+ PTX) ----
__device__ __forceinline__ unsigned long long pack2(float lo, float hi) {
    unsigned long long r;
    asm("mov.b64 %0, {%1, %2};" : "=l"(r)
        : "r"(__float_as_uint(lo)), "r"(__float_as_uint(hi)));
    return r;
}
__device__ __forceinline__ void unpack2(unsigned long long v, float& lo, float& hi) {
    unsigned a, b;
    asm("mov.b64 {%0, %1}, %2;" : "=r"(a), "=r"(b) : "l"(v));
    lo = __uint_as_float(a); hi = __uint_as_float(b);
}
#define FMA2(d, a, b) asm("fma.rn.f32x2 %0, %1, %2, %0;" : "+l"(d) : "l"(a), "l"(b))

__device__ __forceinline__ float wred(float v) {
#pragma unroll
    for (int o = 16; o > 0; o >>= 1) v += __shfl_xor_sync(0xffffffffu, v, o);
    return v;
}

// branch-free exact-grade GELU: A&S 7.1.26 erf (|abs err| <= 1.5e-7)
__device__ __forceinline__ float gelu_fast(float x) {
    const float z = fabsf(x) * 0.70710678118654752440f;
    const float t = __fdividef(1.f, fmaf(0.3275911f, z, 1.f));
    float p = fmaf(t, 1.061405429f, -1.453152027f);
    p = fmaf(t, p, 1.421413741f);
    p = fmaf(t, p, -0.284496736f);
    p = fmaf(t, p, 0.254829592f);
    p *= t;
    const float e  = __expf(-z * z);
    float er = fmaf(-p, e, 1.f);          // erf(|x|/sqrt2)
    er = copysignf(er, x);
    return 0.5f * x * (1.f + er);
}

// One projection for a 64-row tile: X=h@W1+b1; LN; GELU; m=X@W2+b2 -> s_m (64x64, stride 65)
__device__ __forceinline__ void projection(
    const float* __restrict__ hsrc,
    const float* __restrict__ W1, const float* __restrict__ b1,
    const float* __restrict__ lg, const float* __restrict__ lb,
    const float* __restrict__ W2, const float* __restrict__ b2,
    float* smem, float* s_m, int row0, int tid)
{
    float* s_w = smem;                                            // 8192 floats
    unsigned long long* s_h2 = (unsigned long long*)(smem + 8192);// 2048 u64
    float* s_act = smem;                                          // 64 x 260

    const int cg = tid & 31;   // col group: cols 8cg..8cg+7
    const int rg = tid >> 5;   // warp / row group: rows 8rg..8rg+7

    unsigned long long acc[8][4];
#pragma unroll
    for (int i = 0; i < 8; i++)
#pragma unroll
        for (int j = 0; j < 4; j++) acc[i][j] = 0ull;

    // ---- GEMM1: (64x512)@(512x256), k-chunked ----
    for (int kt = 0; kt < D_IN; kt += KC) {
        __syncthreads();
        // stage W1 chunk 32x256 (contiguous)
        {
            const float4* wg = reinterpret_cast<const float4*>(W1 + (size_t)kt * H_MID);
            float4* sw4 = reinterpret_cast<float4*>(s_w);
#pragma unroll
            for (int t = 0; t < 8; t++) sw4[tid + t * NTHR] = wg[tid + t * NTHR];
        }
        // stage h chunk 64x32, duplicated into u64 pairs
#pragma unroll
        for (int t = 0; t < 2; t++) {
            const int idx = tid + t * NTHR;          // 0..511
            const int row = idx >> 3, k4 = idx & 7;
            const float4 g = *reinterpret_cast<const float4*>(
                hsrc + (size_t)(row0 + row) * D_IN + kt + k4 * 4);
            unsigned long long* dst = s_h2 + row * KC + k4 * 4;
            dst[0] = pack2(g.x, g.x); dst[1] = pack2(g.y, g.y);
            dst[2] = pack2(g.z, g.z); dst[3] = pack2(g.w, g.w);
        }
        __syncthreads();

        const unsigned long long* ah = s_h2 + rg * 8 * KC;
#pragma unroll 8
        for (int k = 0; k < KC; k++) {
            const ulonglong2 b01 = *reinterpret_cast<const ulonglong2*>(s_w + k * H_MID + cg * 8);
            const ulonglong2 b23 = *reinterpret_cast<const ulonglong2*>(s_w + k * H_MID + cg * 8 + 4);
#pragma unroll
            for (int i = 0; i < 8; i++) {
                const unsigned long long a = ah[i * KC + k];
                FMA2(acc[i][0], a, b01.x);
                FMA2(acc[i][1], a, b01.y);
                FMA2(acc[i][2], a, b23.x);
                FMA2(acc[i][3], a, b23.y);
            }
        }
    }
    __syncthreads();

    // ---- bias + LayerNorm (row within one warp) + GELU -> act tile ----
    float cb[8], cgm[8], cbe[8];
    *(float4*)&cb[0]  = *(const float4*)(b1 + cg * 8);
    *(float4*)&cb[4]  = *(const float4*)(b1 + cg * 8 + 4);
    *(float4*)&cgm[0] = *(const float4*)(lg + cg * 8);
    *(float4*)&cgm[4] = *(const float4*)(lg + cg * 8 + 4);
    *(float4*)&cbe[0] = *(const float4*)(lb + cg * 8);
    *(float4*)&cbe[4] = *(const float4*)(lb + cg * 8 + 4);

#pragma unroll
    for (int i = 0; i < 8; i++) {
        float v[8];
#pragma unroll
        for (int jp = 0; jp < 4; jp++) unpack2(acc[i][jp], v[2 * jp], v[2 * jp + 1]);
        float s = 0.f, ss = 0.f;
#pragma unroll
        for (int j = 0; j < 8; j++) {
            v[j] += cb[j]; s += v[j]; ss += v[j] * v[j];
        }
        s = wred(s); ss = wred(ss);
        const float mean = s * (1.f / H_MID);
        const float var  = ss * (1.f / H_MID) - mean * mean;
        const float rstd = rsqrtf(var + 1e-5f);
#pragma unroll
        for (int j = 0; j < 8; j++)
            v[j] = gelu_fast((v[j] - mean) * rstd * cgm[j] + cbe[j]);
        float* arow = s_act + (rg * 8 + i) * 260 + cg * 8;
        *(float4*)arow       = make_float4(v[0], v[1], v[2], v[3]);
        *(float4*)(arow + 4) = make_float4(v[4], v[5], v[6], v[7]);
    }
    __syncthreads();

    // ---- GEMM2: (64x256)@(256x64), W2 from L2, f32x2 ----
    const int r2 = tid & 63;        // output row
    const int cq = tid >> 6;        // col quadrant: cols cq*16..+15
    const float* arow = s_act + r2 * 260;
    unsigned long long m2[8];
#pragma unroll
    for (int t = 0; t < 4; t++) {
        const ulonglong2 bb = *reinterpret_cast<const ulonglong2*>(b2 + cq * 16 + t * 4);
        m2[2 * t] = bb.x; m2[2 * t + 1] = bb.y;
    }
#pragma unroll 4
    for (int k = 0; k < H_MID; k++) {
        const float a = arow[k];
        const unsigned long long a2 = pack2(a, a);
        const ulonglong2* wr = reinterpret_cast<const ulonglong2*>(W2 + k * 64 + cq * 16);
        const ulonglong2 q0 = wr[0], q1 = wr[1], q2 = wr[2], q3 = wr[3];
        FMA2(m2[0], a2, q0.x); FMA2(m2[1], a2, q0.y);
        FMA2(m2[2], a2, q1.x); FMA2(m2[3], a2, q1.y);
        FMA2(m2[4], a2, q2.x); FMA2(m2[5], a2, q2.y);
        FMA2(m2[6], a2, q3.x); FMA2(m2[7], a2, q3.y);
    }
#pragma unroll
    for (int t = 0; t < 8; t++) {
        float lo, hi; unpack2(m2[t], lo, hi);
        s_m[r2 * 65 + cq * 16 + 2 * t]     = lo;
        s_m[r2 * 65 + cq * 16 + 2 * t + 1] = hi;
    }
}

__global__ __launch_bounds__(NTHR, 2)
void clifford_fused_kernel(
    const float* __restrict__ hp, const float* __restrict__ hv,
    const float* __restrict__ Wp1, const float* __restrict__ bp1,
    const float* __restrict__ lgp, const float* __restrict__ lbp,
    const float* __restrict__ Wp2, const float* __restrict__ bp2,
    const float* __restrict__ Wv1, const float* __restrict__ bv1,
    const float* __restrict__ lgv, const float* __restrict__ lbv,
    const float* __restrict__ Wv2, const float* __restrict__ bv2,
    const float* __restrict__ T, const float* __restrict__ gw,
    float* __restrict__ out)
{
    extern __shared__ float smem[];
    float* s_T  = smem;            // 95 x 65 (alias region A)
    float* s_u  = smem + 8192;     // 64 x 65 (alias region A)
    float* s_mp = smem + 16640;    // 64 x 65
    float* s_mv = smem + 20800;    // 64 x 65

    const int tid  = threadIdx.x;
    const int row0 = blockIdx.x * BM;

    projection(hp, Wp1, bp1, lgp, lbp, Wp2, bp2, smem, s_mp, row0, tid);
    __syncthreads();
    projection(hv, Wv1, bv1, lgv, lbv, Wv2, bv2, smem, s_mv, row0, tid);
    __syncthreads();

    // stage T (95x64) padded
    for (int t = tid; t < R_OUT * 64; t += NTHR) {
        const int r = t >> 6, q = t & 63;
        s_T[r * 65 + q] = T[t];
    }

    // Triple-product collapse (2 tasks per thread: 64 rows x 8 k)
    {
        const float SG[8][8] = {
            { 1, 1, 1, 1, 1, 1, 1, 1},
            { 1, 1, 1, 1, 1, 1, 1, 1},
            { 1,-1, 1, 1,-1,-1, 1,-1},
            { 1,-1,-1, 1, 1,-1,-1, 1},
            { 1,-1, 1, 1,-1,-1, 1,-1},
            { 1,-1,-1, 1, 1,-1,-1, 1},
            { 1, 1,-1, 1,-1, 1,-1,-1},
            { 1, 1,-1, 1,-1, 1,-1,-1},
        };
        const int XI[8][8] = {
            {0,1,2,3,4,5,6,7},
            {1,0,4,5,2,3,7,6},
            {2,4,0,6,1,7,3,5},
            {3,5,6,0,7,1,2,4},
            {4,2,1,7,0,6,5,3},
            {5,3,7,1,6,0,4,2},
            {6,7,3,2,5,4,0,1},
            {7,6,5,4,3,2,1,0},
        };
        float g[8];
#pragma unroll
        for (int n = 0; n < 8; n++) g[n] = gw[n];

#pragma unroll
        for (int t0 = 0; t0 < 2; t0++) {
            const int t = tid + t0 * NTHR;       // 0..511
            const int row = t >> 3, k = t & 7;
            float p[8], v[8];
#pragma unroll
            for (int i = 0; i < 8; i++) {
                p[i] = s_mp[row * 65 + k * 8 + i];
                v[i] = s_mv[row * 65 + k * 8 + i];
            }
            float w[8];
#pragma unroll
            for (int mm = 0; mm < 8; mm++) {
                float a = 0.f;
#pragma unroll
                for (int jp = 0; jp < 8; jp++)
                    a += SG[mm][jp] * g[XI[mm][jp]] * v[jp];
                w[mm] = a;
            }
#pragma unroll
            for (int j = 0; j < 8; j++) {
                float a = 0.f;
#pragma unroll
                for (int i = 0; i < 8; i++)
                    a += p[i] * SG[i][j] * w[XI[i][j]];
                s_u[row * 65 + k * 8 + j] = a;
            }
        }
    }
    __syncthreads();

    // Final tiny GEMM: out[b,r] = (1/8) * u[b,:] . T[r,:]
    for (int idx = tid; idx < BM * R_OUT; idx += NTHR) {
        const int b = idx / R_OUT;
        const int r = idx - b * R_OUT;
        const float* up = &s_u[b * 65];
        const float* tp = &s_T[r * 65];
        float a = 0.f;
#pragma unroll
        for (int q = 0; q < 64; q++) a += up[q] * tp[q];
        out[(size_t)(row0 + b) * R_OUT + r] = a * 0.125f;
    }
}

extern "C" void kernel_launch(void* const* d_in, const int* in_sizes, int n_in,
                              void* d_out, int out_size)
{
    (void)in_sizes; (void)n_in; (void)out_size;
    const float* hp  = (const float*)d_in[0];
    const float* hv  = (const float*)d_in[1];
    const float* Wp1 = (const float*)d_in[2];
    const float* bp1 = (const float*)d_in[3];
    const float* lgp = (const float*)d_in[4];
    const float* lbp = (const float*)d_in[5];
    const float* Wp2 = (const float*)d_in[6];
    const float* bp2 = (const float*)d_in[7];
    const float* Wv1 = (const float*)d_in[8];
    const float* bv1 = (const float*)d_in[9];
    const float* lgv = (const float*)d_in[10];
    const float* lbv = (const float*)d_in[11];
    const float* Wv2 = (const float*)d_in[12];
    const float* bv2 = (const float*)d_in[13];
    const float* T   = (const float*)d_in[14];
    const float* gw  = (const float*)d_in[15];
    float* out = (float*)d_out;

    cudaFuncSetAttribute(clifford_fused_kernel,
                         cudaFuncAttributeMaxDynamicSharedMemorySize,
                         SMEM_FLOATS * 4);
    clifford_fused_kernel<<<B_TOT / BM, NTHR, SMEM_FLOATS * 4>>>(
        hp, hv, Wp1, bp1, lgp, lbp, Wp2, bp2,
        Wv1, bv1, lgv, lbv, Wv2, bv2, T, gw, out);
}

// round 16
// speedup vs baseline: 2.1829x; 1.6847x over previous
#include <cuda_runtime.h>
#include <cuda_bf16.h>
#include <math.h>
#include <stdint.h>

#define B_TOT   16384
#define D_IN    512
#define H_MID   256
#define R_OUT   95
#define BM      64
#define NTHR    256
#define KC      32
#define NCH     (D_IN / KC)   // 16

// ---- smem byte offsets ----
#define OFF_AHI 0             // 64 x 40 bf16 = 5120
#define OFF_ALO 5120
#define OFF_BHI 10240         // 256 x 40 bf16 = 20480
#define OFF_BLO 30720         // ends 51200
#define OFF_ACT 0             // alias: fp32 64 x 260 = 66560
#define OFF_T   0             // alias after act dead: 95*65*4 = 24700
#define OFF_U   33280         // 64*65*4 = 16640 (within act region)
#define OFF_MP  66560         // 64*65*4 = 16640
#define OFF_MV  83200         // ends 99840
#define SMEM_BYTES 99840

__device__ __forceinline__ uint32_t smem_to_u32(const void* p) {
    uint32_t a;
    asm("{ .reg .u64 t; cvta.to.shared.u64 t, %1; cvt.u32.u64 %0, t; }"
        : "=r"(a) : "l"(p));
    return a;
}

#define LDMX4(r0, r1, r2, r3, addr) \
    asm volatile("ldmatrix.sync.aligned.m8n8.x4.shared.b16 {%0,%1,%2,%3}, [%4];" \
                 : "=r"(r0), "=r"(r1), "=r"(r2), "=r"(r3) : "r"(addr))

#define MMA16816(d, a, b0, b1) \
    asm volatile("mma.sync.aligned.m16n8k16.row.col.f32.bf16.bf16.f32 " \
                 "{%0,%1,%2,%3}, {%4,%5,%6,%7}, {%8,%9}, {%0,%1,%2,%3};" \
                 : "+f"((d)[0]), "+f"((d)[1]), "+f"((d)[2]), "+f"((d)[3]) \
                 : "r"((a)[0]), "r"((a)[1]), "r"((a)[2]), "r"((a)[3]), \
                   "r"(b0), "r"(b1))

// ---- f32x2 packed fp32 helpers ----
__device__ __forceinline__ unsigned long long pack2(float lo, float hi) {
    unsigned long long r;
    asm("mov.b64 %0, {%1, %2};" : "=l"(r)
        : "r"(__float_as_uint(lo)), "r"(__float_as_uint(hi)));
    return r;
}
__device__ __forceinline__ void unpack2(unsigned long long v, float& lo, float& hi) {
    unsigned a, b;
    asm("mov.b64 {%0, %1}, %2;" : "=r"(a), "=r"(b) : "l"(v));
    lo = __uint_as_float(a); hi = __uint_as_float(b);
}
#define FMA2(d, a, b) asm("fma.rn.f32x2 %0, %1, %2, %0;" : "+l"(d) : "l"(a), "l"(b))

__device__ __forceinline__ float wred(float v) {
#pragma unroll
    for (int o = 16; o > 0; o >>= 1) v += __shfl_xor_sync(0xffffffffu, v, o);
    return v;
}

__device__ __forceinline__ float gelu_fast(float x) {
    const float z = fabsf(x) * 0.70710678118654752440f;
    const float t = __fdividef(1.f, fmaf(0.3275911f, z, 1.f));
    float p = fmaf(t, 1.061405429f, -1.453152027f);
    p = fmaf(t, p, 1.421413741f);
    p = fmaf(t, p, -0.284496736f);
    p = fmaf(t, p, 0.254829592f);
    p *= t;
    const float e = __expf(-z * z);
    float er = fmaf(-p, e, 1.f);
    er = copysignf(er, x);
    return 0.5f * x * (1.f + er);
}

__device__ __forceinline__ uint32_t pbf2(__nv_bfloat16 a, __nv_bfloat16 b) {
    __nv_bfloat162 t(a, b);
    return *reinterpret_cast<uint32_t*>(&t);
}

// ============ precompute: W1 -> transposed bf16 hi/lo scratch ============
__device__ __align__(16) __nv_bfloat16 g_hi_p[H_MID * D_IN];
__device__ __align__(16) __nv_bfloat16 g_lo_p[H_MID * D_IN];
__device__ __align__(16) __nv_bfloat16 g_hi_v[H_MID * D_IN];
__device__ __align__(16) __nv_bfloat16 g_lo_v[H_MID * D_IN];

__global__ void split_w1_kernel(const float* __restrict__ Wp1,
                                const float* __restrict__ Wv1) {
    __shared__ float tile[64][65];
    const int b = blockIdx.x;                  // 0..63
    const float* W = (b < 32) ? Wp1 : Wv1;
    __nv_bfloat16* Ghi = (b < 32) ? g_hi_p : g_hi_v;
    __nv_bfloat16* Glo = (b < 32) ? g_lo_p : g_lo_v;
    const int t = b & 31;
    const int kt = (t >> 2) * 64, nt = (t & 3) * 64;
    const int tid = threadIdx.x;
#pragma unroll
    for (int i = 0; i < 16; i++) {
        const int idx = tid + i * 256;
        const int r = idx >> 6, cc = idx & 63;
        tile[r][cc] = W[(size_t)(kt + r) * H_MID + nt + cc];
    }
    __syncthreads();
#pragma unroll
    for (int i = 0; i < 16; i++) {
        const int idx = tid + i * 256;
        const int n = idx >> 6, k = idx & 63;
        const float a = tile[k][n];
        const __nv_bfloat16 hi = __float2bfloat16(a);
        const __nv_bfloat16 lo = __float2bfloat16(a - __bfloat162float(hi));
        Ghi[(size_t)(nt + n) * D_IN + kt + k] = hi;
        Glo[(size_t)(nt + n) * D_IN + kt + k] = lo;
    }
}

// ============ one projection: GEMM1 via HMMA mma.sync, LN+GELU, GEMM2 f32x2 ============
__device__ void projection(
    const float* __restrict__ hsrc,
    const __nv_bfloat16* __restrict__ gBhi, const __nv_bfloat16* __restrict__ gBlo,
    const float* __restrict__ b1, const float* __restrict__ lg,
    const float* __restrict__ lb,
    const float* __restrict__ W2, const float* __restrict__ b2,
    char* smc, uint32_t sb, float* s_m, int row0, int tid)
{
    const int w = tid >> 5, l = tid & 31;
    const int wm = (w & 1) * 32;       // warp M offset (2 warps x 32 rows)
    const int wn = (w >> 1) * 64;      // warp N offset (4 warps x 64 cols)

    // ldmatrix lane address components
    const int arow = l & 15, acol = (l >> 4) * 8;            // A: 16x16 tile
    const int brow = ((l >> 4) & 1) * 8 + (l & 7);           // B: n16 x k16 tile
    const int bcol = ((l >> 3) & 1) * 8;

    float acc[2][8][4];
#pragma unroll
    for (int mt = 0; mt < 2; mt++)
#pragma unroll
        for (int n = 0; n < 8; n++)
#pragma unroll
            for (int q = 0; q < 4; q++) acc[mt][n][q] = 0.f;

    for (int c = 0; c < NCH; ++c) {
        const int kt = c * KC;
        __syncthreads();
        // ---- stage A = h chunk (64 x 32 fp32 -> bf16 hi/lo, stride 40 bf16)
#pragma unroll
        for (int t = 0; t < 2; ++t) {
            const int idx = tid + t * NTHR;        // 0..511 : 64 rows x 8 col4
            const int r = idx >> 3, c4 = idx & 7;
            const float4 g = *reinterpret_cast<const float4*>(
                hsrc + (size_t)(row0 + r) * D_IN + kt + c4 * 4);
            const __nv_bfloat16 h0 = __float2bfloat16(g.x);
            const __nv_bfloat16 h1 = __float2bfloat16(g.y);
            const __nv_bfloat16 h2 = __float2bfloat16(g.z);
            const __nv_bfloat16 h3 = __float2bfloat16(g.w);
            const __nv_bfloat16 l0 = __float2bfloat16(g.x - __bfloat162float(h0));
            const __nv_bfloat16 l1 = __float2bfloat16(g.y - __bfloat162float(h1));
            const __nv_bfloat16 l2 = __float2bfloat16(g.z - __bfloat162float(h2));
            const __nv_bfloat16 l3 = __float2bfloat16(g.w - __bfloat162float(h3));
            const int off = r * 80 + c4 * 8;
            *reinterpret_cast<uint2*>(smc + OFF_AHI + off) = make_uint2(pbf2(h0, h1), pbf2(h2, h3));
            *reinterpret_cast<uint2*>(smc + OFF_ALO + off) = make_uint2(pbf2(l0, l1), pbf2(l2, l3));
        }
        // ---- stage B = W1T chunk (256 x 32 bf16 hi/lo, stride 40 bf16)
#pragma unroll
        for (int t = 0; t < 4; ++t) {
            const int idx = tid + t * NTHR;        // 0..1023 : 256 rows x 4 uint4
            const int n = idx >> 2, k8 = idx & 3;
            const uint4 vh = *(reinterpret_cast<const uint4*>(gBhi + (size_t)n * D_IN + kt) + k8);
            const uint4 vl = *(reinterpret_cast<const uint4*>(gBlo + (size_t)n * D_IN + kt) + k8);
            const int off = n * 80 + k8 * 16;
            *reinterpret_cast<uint4*>(smc + OFF_BHI + off) = vh;
            *reinterpret_cast<uint4*>(smc + OFF_BLO + off) = vl;
        }
        __syncthreads();

        // ---- HMMA mainloop over 2 k16 steps
#pragma unroll
        for (int ks = 0; ks < KC; ks += 16) {
            uint32_t ah[2][4], al[2][4];
#pragma unroll
            for (int mt = 0; mt < 2; mt++) {
                const uint32_t aoff = (uint32_t)((wm + mt * 16 + arow) * 80 + (acol + ks) * 2);
                LDMX4(ah[mt][0], ah[mt][1], ah[mt][2], ah[mt][3], sb + OFF_AHI + aoff);
                LDMX4(al[mt][0], al[mt][1], al[mt][2], al[mt][3], sb + OFF_ALO + aoff);
            }
#pragma unroll
            for (int ng = 0; ng < 4; ng++) {
                const uint32_t boff = (uint32_t)((wn + ng * 16 + brow) * 80 + (bcol + ks) * 2);
                uint32_t bh[4], bl[4];
                LDMX4(bh[0], bh[1], bh[2], bh[3], sb + OFF_BHI + boff);
                LDMX4(bl[0], bl[1], bl[2], bl[3], sb + OFF_BLO + boff);
#pragma unroll
                for (int mt = 0; mt < 2; mt++) {
#pragma unroll
                    for (int nt = 0; nt < 2; nt++) {
                        float* d = acc[mt][ng * 2 + nt];
                        MMA16816(d, ah[mt], bh[2 * nt], bh[2 * nt + 1]);
                        MMA16816(d, ah[mt], bl[2 * nt], bl[2 * nt + 1]);
                        MMA16816(d, al[mt], bh[2 * nt], bh[2 * nt + 1]);
                    }
                }
            }
        }
    }
    __syncthreads();     // all warps done reading A/B smem before act overwrite

    // ---- write raw C to act (fp32, stride 260) ----
    float* act = reinterpret_cast<float*>(smc + OFF_ACT);
    {
        const int g = l >> 2, tg = l & 3;
#pragma unroll
        for (int mt = 0; mt < 2; mt++)
#pragma unroll
            for (int n = 0; n < 8; n++) {
                const int row = wm + mt * 16 + g;
                const int col = wn + n * 8 + 2 * tg;
                const float* d = acc[mt][n];
                act[row * 260 + col]           = d[0];
                act[row * 260 + col + 1]       = d[1];
                act[(row + 8) * 260 + col]     = d[2];
                act[(row + 8) * 260 + col + 1] = d[3];
            }
    }
    __syncthreads();

    // ---- bias + LayerNorm + GELU (warp w owns rows w*8..w*8+7) ----
#pragma unroll
    for (int i = 0; i < 8; ++i) {
        const int r = w * 8 + i;
        float x[8];
        const float4 u0 = *reinterpret_cast<const float4*>(act + r * 260 + l * 8);
        const float4 u1 = *reinterpret_cast<const float4*>(act + r * 260 + l * 8 + 4);
        x[0] = u0.x; x[1] = u0.y; x[2] = u0.z; x[3] = u0.w;
        x[4] = u1.x; x[5] = u1.y; x[6] = u1.z; x[7] = u1.w;
        float s = 0.f, ss = 0.f;
#pragma unroll
        for (int j = 0; j < 8; j++) {
            x[j] += __ldg(&b1[l * 8 + j]);
            s += x[j]; ss += x[j] * x[j];
        }
        s = wred(s); ss = wred(ss);
        const float mean = s * (1.f / H_MID);
        const float var  = ss * (1.f / H_MID) - mean * mean;
        const float rstd = rsqrtf(var + 1e-5f);
#pragma unroll
        for (int j = 0; j < 8; j++) {
            const float y = (x[j] - mean) * rstd * __ldg(&lg[l * 8 + j]) + __ldg(&lb[l * 8 + j]);
            x[j] = gelu_fast(y);
        }
        *reinterpret_cast<float4*>(act + r * 260 + l * 8)     = make_float4(x[0], x[1], x[2], x[3]);
        *reinterpret_cast<float4*>(act + r * 260 + l * 8 + 4) = make_float4(x[4], x[5], x[6], x[7]);
    }
    __syncthreads();

    // ---- GEMM2: (64 x 256) @ (256 x 64), f32x2, W2 hot in L2 ----
    const int r2 = tid & 63;
    const int cq = tid >> 6;                // 0..3 -> cols cq*16..+15
    const float* arw = act + r2 * 260;
    unsigned long long m2[8];
#pragma unroll
    for (int t = 0; t < 4; t++) {
        const ulonglong2 bb = *reinterpret_cast<const ulonglong2*>(b2 + cq * 16 + t * 4);
        m2[2 * t] = bb.x; m2[2 * t + 1] = bb.y;
    }
#pragma unroll 4
    for (int k = 0; k < H_MID; k++) {
        const float a = arw[k];
        const unsigned long long a2 = pack2(a, a);
        const ulonglong2* wr = reinterpret_cast<const ulonglong2*>(W2 + k * 64 + cq * 16);
#pragma unroll
        for (int q = 0; q < 4; q++) {
            const ulonglong2 qq = wr[q];
            FMA2(m2[2 * q], a2, qq.x);
            FMA2(m2[2 * q + 1], a2, qq.y);
        }
    }
    __syncthreads();                         // act fully read before caller reuses region
#pragma unroll
    for (int t = 0; t < 8; t++) {
        float lo, hi; unpack2(m2[t], lo, hi);
        s_m[r2 * 65 + cq * 16 + 2 * t]     = lo;
        s_m[r2 * 65 + cq * 16 + 2 * t + 1] = hi;
    }
}

// ============ main fused kernel ============
__global__ __launch_bounds__(NTHR, 2)
void clifford_fused_kernel(
    const float* __restrict__ hp, const float* __restrict__ hv,
    const float* __restrict__ bp1, const float* __restrict__ lgp,
    const float* __restrict__ lbp,
    const float* __restrict__ Wp2, const float* __restrict__ bp2,
    const float* __restrict__ bv1, const float* __restrict__ lgv,
    const float* __restrict__ lbv,
    const float* __restrict__ Wv2, const float* __restrict__ bv2,
    const float* __restrict__ T, const float* __restrict__ gw,
    float* __restrict__ out)
{
    extern __shared__ char smc[];
    const uint32_t sb = smem_to_u32(smc);
    const int tid = threadIdx.x;
    const int row0 = blockIdx.x * BM;

    float* s_mp = reinterpret_cast<float*>(smc + OFF_MP);
    float* s_mv = reinterpret_cast<float*>(smc + OFF_MV);

    projection(hp, g_hi_p, g_lo_p, bp1, lgp, lbp, Wp2, bp2, smc, sb, s_mp, row0, tid);
    __syncthreads();
    projection(hv, g_hi_v, g_lo_v, bv1, lgv, lbv, Wv2, bv2, smc, sb, s_mv, row0, tid);
    __syncthreads();

    // stage T (95 x 64) padded stride 65 (aliases dead act region)
    float* s_T = reinterpret_cast<float*>(smc + OFF_T);
    float* s_u = reinterpret_cast<float*>(smc + OFF_U);
    for (int t = tid; t < R_OUT * 64; t += NTHR) {
        const int r = t >> 6, q = t & 63;
        s_T[r * 65 + q] = T[t];
    }

    // Triple-product collapse: 512 tasks = 64 rows x 8 k
    {
        const float SG[8][8] = {
            { 1, 1, 1, 1, 1, 1, 1, 1},
            { 1, 1, 1, 1, 1, 1, 1, 1},
            { 1,-1, 1, 1,-1,-1, 1,-1},
            { 1,-1,-1, 1, 1,-1,-1, 1},
            { 1,-1, 1, 1,-1,-1, 1,-1},
            { 1,-1,-1, 1, 1,-1,-1, 1},
            { 1, 1,-1, 1,-1, 1,-1,-1},
            { 1, 1,-1, 1,-1, 1,-1,-1},
        };
        const int XI[8][8] = {
            {0,1,2,3,4,5,6,7},
            {1,0,4,5,2,3,7,6},
            {2,4,0,6,1,7,3,5},
            {3,5,6,0,7,1,2,4},
            {4,2,1,7,0,6,5,3},
            {5,3,7,1,6,0,4,2},
            {6,7,3,2,5,4,0,1},
            {7,6,5,4,3,2,1,0},
        };
        float g[8];
#pragma unroll
        for (int n = 0; n < 8; n++) g[n] = gw[n];
#pragma unroll
        for (int t0 = 0; t0 < 2; t0++) {
            const int t = tid + t0 * NTHR;       // 0..511
            const int row = t >> 3, k = t & 7;
            float p[8], v[8];
#pragma unroll
            for (int i = 0; i < 8; i++) {
                p[i] = s_mp[row * 65 + k * 8 + i];
                v[i] = s_mv[row * 65 + k * 8 + i];
            }
            float wv[8];
#pragma unroll
            for (int mm = 0; mm < 8; mm++) {
                float a = 0.f;
#pragma unroll
                for (int jp = 0; jp < 8; jp++)
                    a += SG[mm][jp] * g[XI[mm][jp]] * v[jp];
                wv[mm] = a;
            }
#pragma unroll
            for (int j = 0; j < 8; j++) {
                float a = 0.f;
#pragma unroll
                for (int i = 0; i < 8; i++)
                    a += p[i] * SG[i][j] * wv[XI[i][j]];
                s_u[row * 65 + k * 8 + j] = a;
            }
        }
    }
    __syncthreads();

    // Final: out[b,r] = (1/8) * u[b,:] . T[r,:]
    for (int idx = tid; idx < BM * R_OUT; idx += NTHR) {
        const int b = idx / R_OUT;
        const int r = idx - b * R_OUT;
        const float* up = &s_u[b * 65];
        const float* tp = &s_T[r * 65];
        float a = 0.f;
#pragma unroll
        for (int q = 0; q < 64; q++) a += up[q] * tp[q];
        out[(size_t)(row0 + b) * R_OUT + r] = a * 0.125f;
    }
}

extern "C" void kernel_launch(void* const* d_in, const int* in_sizes, int n_in,
                              void* d_out, int out_size)
{
    (void)in_sizes; (void)n_in; (void)out_size;
    const float* hp  = (const float*)d_in[0];
    const float* hv  = (const float*)d_in[1];
    const float* Wp1 = (const float*)d_in[2];
    const float* bp1 = (const float*)d_in[3];
    const float* lgp = (const float*)d_in[4];
    const float* lbp = (const float*)d_in[5];
    const float* Wp2 = (const float*)d_in[6];
    const float* bp2 = (const float*)d_in[7];
    const float* Wv1 = (const float*)d_in[8];
    const float* bv1 = (const float*)d_in[9];
    const float* lgv = (const float*)d_in[10];
    const float* lbv = (const float*)d_in[11];
    const float* Wv2 = (const float*)d_in[12];
    const float* bv2 = (const float*)d_in[13];
    const float* T   = (const float*)d_in[14];
    const float* gw  = (const float*)d_in[15];
    float* out = (float*)d_out;

    split_w1_kernel<<<64, 256>>>(Wp1, Wv1);

    cudaFuncSetAttribute(clifford_fused_kernel,
                         cudaFuncAttributeMaxDynamicSharedMemorySize, SMEM_BYTES);
    clifford_fused_kernel<<<B_TOT / BM, NTHR, SMEM_BYTES>>>(
        hp, hv, bp1, lgp, lbp, Wp2, bp2,
        bv1, lgv, lbv, Wv2, bv2, T, gw, out);
}